// round 2
// baseline (speedup 1.0000x reference)
#include <cuda_runtime.h>
#include <math.h>

// ---------------------------------------------------------------------------
// In2MA fused window kernel (fp32 baseline).
// One CTA per 8x8 window (4096 CTAs), 256 threads.
// All intermediates live in shared memory; weights staged via float4 copies.
// ---------------------------------------------------------------------------

namespace {

constexpr int P64 = 65;   // padded row stride for 64-wide buffers (odd -> conflict free)
constexpr int P32 = 33;   // padded row stride for 32-wide buffers

// shared memory layout (in floats)
constexpr int OFF_A  = 0;                    // xf -> cat -> xv2            [64][65]
constexpr int OFF_B  = OFF_A + 64 * P64;     // v1 -> out1 -> out2          [64][65]
constexpr int OFF_C  = OFF_B + 64 * P64;     // pan_q | pan_k               [64][65]
constexpr int OFF_D  = OFF_C + 64 * P64;     // q1c | k1c -> xk2            [64][65]
constexpr int OFF_E  = OFF_D + 64 * P64;     // pan -> cos scratch          [64][33]
constexpr int OFF_WA = OFF_E + 64 * P32;     // weight buffer A (4096 f)
constexpr int OFF_WB = OFF_WA + 4096;        // weight buffer B (4096 f)
constexpr int SMEM_FLOATS = OFF_WB + 4096;   // = 26944 floats
constexpr int SMEM_BYTES  = SMEM_FLOATS * 4; // = 107776 bytes

constexpr float SCALE = 0.35355339059327373f; // 1/sqrt(8), both attn scales

__device__ __forceinline__ void cpw(float* dst, const float* src, int n, int tid) {
    // n is a multiple of 1024; 256 threads * float4
    for (int i = tid * 4; i < n; i += 1024) {
        *reinterpret_cast<float4*>(dst + i) =
            *reinterpret_cast<const float4*>(src + i);
    }
}

// out[t][o] = sum_k in[t][k] * W[o][k];  64 rows t, O cols, weights row-major [O][K].
// Thread microtile: 4 rows x (O/16) cols.
template <int K, int O>
__device__ __forceinline__ void gemm_sm(const float* __restrict__ in_s, int inPad,
                                        const float* __restrict__ w_s,
                                        float* __restrict__ out_s, int outPad, int tid) {
    const int t0 = (tid & 15) * 4;
    const int oc = tid >> 4;            // 0..15
    constexpr int OC = O / 16;
    float acc[4][OC];
#pragma unroll
    for (int i = 0; i < 4; i++)
#pragma unroll
        for (int j = 0; j < OC; j++) acc[i][j] = 0.0f;

    const float* ip = in_s + t0 * inPad;
    const float* wp = w_s + oc * OC * K;
#pragma unroll 4
    for (int k = 0; k < K; k++) {
        float a0 = ip[k];
        float a1 = ip[inPad + k];
        float a2 = ip[2 * inPad + k];
        float a3 = ip[3 * inPad + k];
#pragma unroll
        for (int j = 0; j < OC; j++) {
            float w = wp[j * K + k];
            acc[0][j] += a0 * w;
            acc[1][j] += a1 * w;
            acc[2][j] += a2 * w;
            acc[3][j] += a3 * w;
        }
    }
#pragma unroll
    for (int i = 0; i < 4; i++)
#pragma unroll
        for (int j = 0; j < OC; j++)
            out_s[(t0 + i) * outPad + oc * OC + j] = acc[i][j];
}

__global__ void __launch_bounds__(256, 2)
in2ma_kernel(const float* __restrict__ x,      // (4,64,256,256)
             const float* __restrict__ panf,   // (4,32,256,256)
             const float* __restrict__ Wpq,    // (32,32)
             const float* __restrict__ Wpk,    // (32,32)
             const float* __restrict__ Wv1,    // (64,64)
             const float* __restrict__ Wv2,    // (64,64)
             const float* __restrict__ Wk2,    // (32,64)
             const float* __restrict__ Wq1c,   // (32,64)
             const float* __restrict__ Wk1c,   // (32,64)
             const float* __restrict__ Wio,    // (64,64) inner_out
             const float* __restrict__ Wto,    // (64,64) inter_out
             const float* __restrict__ posI,   // (1,8,64,64)
             const float* __restrict__ posC,   // (1,8,32,32)
             float* __restrict__ out)          // (4,64,256,256)
{
    extern __shared__ float sm[];
    float* A  = sm + OFF_A;
    float* Bv = sm + OFF_B;
    float* C  = sm + OFF_C;
    float* D  = sm + OFF_D;
    float* E  = sm + OFF_E;
    float* WA = sm + OFF_WA;
    float* WB = sm + OFF_WB;

    const int tid = threadIdx.x;
    const int widx = blockIdx.x;
    const int b  = widx >> 10;
    const int hi = (widx >> 5) & 31;
    const int wi = widx & 31;
    const int rowbase = hi * 8;
    const int colbase = wi * 8;

    // ---- load window: xf[t][ch] (64x64), pan[t][ch] (64x32); stage GEMM1 weights
    {
        const float* xb = x + b * (64 * 256 * 256);
        for (int e = tid; e < 4096; e += 256) {
            int ch = e >> 6, t = e & 63;
            A[t * P64 + ch] = xb[(ch * 256 + rowbase + (t >> 3)) * 256 + colbase + (t & 7)];
        }
        const float* pb = panf + b * (32 * 256 * 256);
        for (int e = tid; e < 2048; e += 256) {
            int ch = e >> 6, t = e & 63;
            E[t * P32 + ch] = pb[(ch * 256 + rowbase + (t >> 3)) * 256 + colbase + (t & 7)];
        }
        cpw(WA,        Wpq, 1024, tid);
        cpw(WA + 1024, Wpk, 1024, tid);
    }
    __syncthreads();

    // ---- GEMM1: pan_q | pan_k  (C cols 0..31 = q, 32..63 = k), K=32
    gemm_sm<32, 64>(E, P32, WA, C, P64, tid);
    __syncthreads();

    cpw(WA, Wv1, 4096, tid);
    cpw(WB,        Wq1c, 2048, tid);
    cpw(WB + 2048, Wk1c, 2048, tid);
    __syncthreads();

    // ---- GEMM2: x_v1 -> Bv ; q1c|k1c -> D
    gemm_sm<64, 64>(A, P64, WA, Bv, P64, tid);
    gemm_sm<64, 64>(A, P64, WB, D,  P64, tid);
    __syncthreads();

    // stage W_inner_out for GEMM3 while attention runs (WA not read until next sync)
    cpw(WA, Wio, 4096, tid);

    const int h = tid >> 5;      // warp = head
    const int lane = tid & 31;

    // ---- inner (pan) attention: warp h, rows i = lane, lane+32. cat cols 0..31 in A.
    {
        const float* pos = posI + h * 4096;
#pragma unroll 1
        for (int p = 0; p < 2; p++) {
            const int i = p * 32 + lane;
            const float* qr = C + i * P64 + h * 4;
            float q0 = qr[0] * SCALE, q1 = qr[1] * SCALE, q2 = qr[2] * SCALE, q3 = qr[3] * SCALE;
            float l[64];
            const float4* pr = reinterpret_cast<const float4*>(pos + i * 64);
#pragma unroll
            for (int j4 = 0; j4 < 16; j4++) {
                float4 pv = pr[j4];
                float pvv[4] = {pv.x, pv.y, pv.z, pv.w};
#pragma unroll
                for (int jj = 0; jj < 4; jj++) {
                    int j = j4 * 4 + jj;
                    const float* kr = C + j * P64 + 32 + h * 4;
                    float s = q0 * kr[0] + q1 * kr[1] + q2 * kr[2] + q3 * kr[3];
                    l[j] = s + pvv[jj];
                }
            }
            float m = l[0];
#pragma unroll
            for (int j = 1; j < 64; j++) m = fmaxf(m, l[j]);
            float ssum = 0.0f;
#pragma unroll
            for (int j = 0; j < 64; j++) { l[j] = __expf(l[j] - m); ssum += l[j]; }
            float inv = 1.0f / ssum;
            float a0 = 0.f, a1 = 0.f, a2 = 0.f, a3 = 0.f;
#pragma unroll
            for (int j = 0; j < 64; j++) {
                const float* vr = Bv + j * P64 + h * 4;   // v1_pan = v1 cols 0..31
                a0 += l[j] * vr[0];
                a1 += l[j] * vr[1];
                a2 += l[j] * vr[2];
                a3 += l[j] * vr[3];
            }
            float* orow = A + i * P64 + h * 4;
            orow[0] = a0 * inv; orow[1] = a1 * inv; orow[2] = a2 * inv; orow[3] = a3 * inv;
        }
    }

    // ---- color attention: warp h, "row" i = lane (feature index 0..31). cat cols 32..63.
    {
        float qd[8];
#pragma unroll
        for (int d = 0; d < 8; d++)
            qd[d] = D[(h * 8 + d) * P64 + lane] * SCALE;     // q1c[token h*8+d][feat i]
        float l2[32];
        const float4* pr = reinterpret_cast<const float4*>(posC + h * 1024 + lane * 32);
#pragma unroll
        for (int j4 = 0; j4 < 8; j4++) {
            float4 pv = pr[j4];
            float pvv[4] = {pv.x, pv.y, pv.z, pv.w};
#pragma unroll
            for (int jj = 0; jj < 4; jj++) {
                int j = j4 * 4 + jj;
                float s = 0.0f;
#pragma unroll
                for (int d = 0; d < 8; d++)
                    s += qd[d] * D[(h * 8 + d) * P64 + 32 + j];   // k1c
                l2[j] = s + pvv[jj];
            }
        }
        float m = l2[0];
#pragma unroll
        for (int j = 1; j < 32; j++) m = fmaxf(m, l2[j]);
        float ssum = 0.0f;
#pragma unroll
        for (int j = 0; j < 32; j++) { l2[j] = __expf(l2[j] - m); ssum += l2[j]; }
        float inv = 1.0f / ssum;
        float accd[8];
#pragma unroll
        for (int d = 0; d < 8; d++) accd[d] = 0.0f;
#pragma unroll
        for (int j = 0; j < 32; j++) {
            float p = l2[j];
#pragma unroll
            for (int d = 0; d < 8; d++)
                accd[d] += p * Bv[(h * 8 + d) * P64 + 32 + j];   // v1_color = v1 cols 32..63
        }
#pragma unroll
        for (int d = 0; d < 8; d++)
            A[(h * 8 + d) * P64 + 32 + lane] = accd[d] * inv;    // out_color[t][i]
    }
    __syncthreads();

    // ---- GEMM3: out1 = cat @ W_inner_out^T  -> Bv
    gemm_sm<64, 64>(A, P64, WA, Bv, P64, tid);
    __syncthreads();

    cpw(WA, Wv2, 4096, tid);
    cpw(WB, Wk2, 2048, tid);
    __syncthreads();

    // ---- GEMM4: xv2 -> A ; xk2 -> D cols 0..31
    gemm_sm<64, 64>(Bv, P64, WA, A, P64, tid);
    gemm_sm<64, 32>(Bv, P64, WB, D, P64, tid);
    __syncthreads();

    // stage W_inter_out; compute cosine gate -> E[h*64+t]
    cpw(WA, Wto, 4096, tid);
    for (int idx = tid; idx < 512; idx += 256) {
        int hh = idx >> 6, t = idx & 63;
        const float* qr = C + t * P64 + hh * 4;   // pan_q
        const float* kr = D + t * P64 + hh * 4;   // xk2
        float dot = 0.f, qq = 0.f, kk = 0.f;
#pragma unroll
        for (int d = 0; d < 4; d++) {
            float qv = qr[d], kv = kr[d];
            dot += qv * kv; qq += qv * qv; kk += kv * kv;
        }
        E[idx] = dot / (sqrtf(qq) * sqrtf(kk));
    }
    __syncthreads();

    // ---- out2[t][f] = cos[f/8][t] * xv2[t][f]  -> Bv
    for (int e = tid; e < 4096; e += 256) {
        int f = e >> 6, t = e & 63;
        Bv[t * P64 + f] = E[(f >> 3) * 64 + t] * A[t * P64 + f];
    }
    __syncthreads();

    // ---- GEMM5: out3 = out2 @ W_inter_out^T, stored straight to global
    {
        const int t0 = (tid & 15) * 4;
        const int oc = tid >> 4;
        float acc[4][4];
#pragma unroll
        for (int i = 0; i < 4; i++)
#pragma unroll
            for (int j = 0; j < 4; j++) acc[i][j] = 0.0f;
        const float* ip = Bv + t0 * P64;
        const float* wp = WA + oc * 4 * 64;
#pragma unroll 4
        for (int k = 0; k < 64; k++) {
            float a0 = ip[k];
            float a1 = ip[P64 + k];
            float a2 = ip[2 * P64 + k];
            float a3 = ip[3 * P64 + k];
#pragma unroll
            for (int j = 0; j < 4; j++) {
                float w = wp[j * 64 + k];
                acc[0][j] += a0 * w;
                acc[1][j] += a1 * w;
                acc[2][j] += a2 * w;
                acc[3][j] += a3 * w;
            }
        }
        float* ob = out + b * (64 * 256 * 256);
#pragma unroll
        for (int i = 0; i < 4; i++) {
            int t = t0 + i;
            int gr = rowbase + (t >> 3);
            int gc = colbase + (t & 7);
#pragma unroll
            for (int j = 0; j < 4; j++) {
                int o = oc * 4 + j;
                ob[(o * 256 + gr) * 256 + gc] = acc[i][j];
            }
        }
    }
}

} // anonymous namespace

extern "C" void kernel_launch(void* const* d_in, const int* in_sizes, int n_in,
                              void* d_out, int out_size) {
    (void)in_sizes; (void)n_in; (void)out_size;
    const float* x    = (const float*)d_in[0];
    const float* panf = (const float*)d_in[1];
    const float* Wpq  = (const float*)d_in[2];
    const float* Wpk  = (const float*)d_in[3];
    const float* Wv1  = (const float*)d_in[4];
    const float* Wv2  = (const float*)d_in[5];
    const float* Wk2  = (const float*)d_in[6];
    const float* Wq1c = (const float*)d_in[7];
    const float* Wk1c = (const float*)d_in[8];
    const float* Wio  = (const float*)d_in[9];
    const float* Wto  = (const float*)d_in[10];
    const float* posI = (const float*)d_in[11];
    const float* posC = (const float*)d_in[12];
    float* out = (float*)d_out;

    cudaFuncSetAttribute(in2ma_kernel, cudaFuncAttributeMaxDynamicSharedMemorySize, SMEM_BYTES);
    in2ma_kernel<<<4096, 256, SMEM_BYTES>>>(x, panf, Wpq, Wpk, Wv1, Wv2, Wk2,
                                            Wq1c, Wk1c, Wio, Wto, posI, posC, out);
}

// round 8
// speedup vs baseline: 1.4701x; 1.4701x over previous
#include <cuda_runtime.h>
#include <math.h>

// ---------------------------------------------------------------------------
// In2MA fused window kernel, v3: vectorized conflict-free LDS (float4)
// + fused dual-GEMMs sharing input loads (GEMM2 pair, GEMM4 pair).
// One CTA per 8x8 window (4096 CTAs), 256 threads.
// ---------------------------------------------------------------------------

namespace {

constexpr int P64 = 68;   // padded stride: multiple of 4 (float4), 17 16B-groups -> conflict free
constexpr int P32 = 36;   // padded stride for 32-wide pan buffer

// shared memory layout (in floats)
constexpr int OFF_A  = 0;                    // xf -> cat -> xv2            [64][68]
constexpr int OFF_B  = OFF_A + 64 * P64;     // v1 -> out1 -> out2          [64][68]
constexpr int OFF_C  = OFF_B + 64 * P64;     // pan_q | pan_k               [64][68]
constexpr int OFF_D  = OFF_C + 64 * P64;     // q1c | k1c -> xk2            [64][68]
constexpr int OFF_E  = OFF_D + 64 * P64;     // pan -> cos scratch          [64][36]
constexpr int OFF_WA = OFF_E + 64 * P32;     // weight buffer A (4096 f)
constexpr int OFF_WB = OFF_WA + 4096;        // weight buffer B (4096 f)
constexpr int SMEM_FLOATS = OFF_WB + 4096;   // 27904 floats
constexpr int SMEM_BYTES  = SMEM_FLOATS * 4; // 111616 bytes (2 CTAs/SM)

constexpr float SCALE = 0.35355339059327373f; // 1/sqrt(8), both attn scales

__device__ __forceinline__ void cpw(float* dst, const float* src, int n, int tid) {
    for (int i = tid * 4; i < n; i += 1024) {
        *reinterpret_cast<float4*>(dst + i) =
            *reinterpret_cast<const float4*>(src + i);
    }
}

// out[t][o] = sum_k in[t][k] * W[o][k];  64 rows, O cols, W row-major [O][K].
// Thread tile: rows {r0, r0+16, r0+32, r0+48} x OC cols; k vectorized by 4.
template <int K, int O>
__device__ __forceinline__ void gemm_sm(const float* __restrict__ in_s, int inPad,
                                        const float* __restrict__ w_s,
                                        float* __restrict__ out_s, int outPad, int tid) {
    const int r0 = tid & 15;
    const int oc = tid >> 4;            // 0..15
    constexpr int OC = O / 16;
    float acc[4][OC];
#pragma unroll
    for (int i = 0; i < 4; i++)
#pragma unroll
        for (int j = 0; j < OC; j++) acc[i][j] = 0.0f;

#pragma unroll
    for (int k4 = 0; k4 < K / 4; k4++) {
        float4 a[4];
#pragma unroll
        for (int i = 0; i < 4; i++)
            a[i] = *reinterpret_cast<const float4*>(in_s + (r0 + 16 * i) * inPad + 4 * k4);
#pragma unroll
        for (int j = 0; j < OC; j++) {
            float4 w = *reinterpret_cast<const float4*>(w_s + (oc * OC + j) * K + 4 * k4);
#pragma unroll
            for (int i = 0; i < 4; i++) {
                acc[i][j] += a[i].x * w.x;
                acc[i][j] += a[i].y * w.y;
                acc[i][j] += a[i].z * w.z;
                acc[i][j] += a[i].w * w.w;
            }
        }
    }
#pragma unroll
    for (int i = 0; i < 4; i++) {
        if constexpr (OC == 4) {
            float4 o4 = make_float4(acc[i][0], acc[i][1], acc[i][2], acc[i][3]);
            *reinterpret_cast<float4*>(out_s + (r0 + 16 * i) * outPad + oc * 4) = o4;
        } else {
#pragma unroll
            for (int j = 0; j < OC; j++)
                out_s[(r0 + 16 * i) * outPad + oc * OC + j] = acc[i][j];
        }
    }
}

// Two GEMMs sharing the same input rows: out1 = in @ W1^T, out2 = in @ W2^T.
// Input rows loaded ONCE per k-step, applied to both weight sets.
template <int K, int O1, int O2>
__device__ __forceinline__ void gemm_sm_dual(const float* __restrict__ in_s, int inPad,
                                             const float* __restrict__ w1_s,
                                             const float* __restrict__ w2_s,
                                             float* __restrict__ out1_s,
                                             float* __restrict__ out2_s,
                                             int outPad, int tid) {
    const int r0 = tid & 15;
    const int oc = tid >> 4;            // 0..15
    constexpr int OC1 = O1 / 16;
    constexpr int OC2 = O2 / 16;
    float acc1[4][OC1];
    float acc2[4][OC2];
#pragma unroll
    for (int i = 0; i < 4; i++) {
#pragma unroll
        for (int j = 0; j < OC1; j++) acc1[i][j] = 0.0f;
#pragma unroll
        for (int j = 0; j < OC2; j++) acc2[i][j] = 0.0f;
    }

#pragma unroll
    for (int k4 = 0; k4 < K / 4; k4++) {
        float4 a[4];
#pragma unroll
        for (int i = 0; i < 4; i++)
            a[i] = *reinterpret_cast<const float4*>(in_s + (r0 + 16 * i) * inPad + 4 * k4);
#pragma unroll
        for (int j = 0; j < OC1; j++) {
            float4 w = *reinterpret_cast<const float4*>(w1_s + (oc * OC1 + j) * K + 4 * k4);
#pragma unroll
            for (int i = 0; i < 4; i++) {
                acc1[i][j] += a[i].x * w.x;
                acc1[i][j] += a[i].y * w.y;
                acc1[i][j] += a[i].z * w.z;
                acc1[i][j] += a[i].w * w.w;
            }
        }
#pragma unroll
        for (int j = 0; j < OC2; j++) {
            float4 w = *reinterpret_cast<const float4*>(w2_s + (oc * OC2 + j) * K + 4 * k4);
#pragma unroll
            for (int i = 0; i < 4; i++) {
                acc2[i][j] += a[i].x * w.x;
                acc2[i][j] += a[i].y * w.y;
                acc2[i][j] += a[i].z * w.z;
                acc2[i][j] += a[i].w * w.w;
            }
        }
    }
#pragma unroll
    for (int i = 0; i < 4; i++) {
        if constexpr (OC1 == 4) {
            float4 o4 = make_float4(acc1[i][0], acc1[i][1], acc1[i][2], acc1[i][3]);
            *reinterpret_cast<float4*>(out1_s + (r0 + 16 * i) * outPad + oc * 4) = o4;
        } else {
#pragma unroll
            for (int j = 0; j < OC1; j++)
                out1_s[(r0 + 16 * i) * outPad + oc * OC1 + j] = acc1[i][j];
        }
        if constexpr (OC2 == 4) {
            float4 o4 = make_float4(acc2[i][0], acc2[i][1], acc2[i][2], acc2[i][3]);
            *reinterpret_cast<float4*>(out2_s + (r0 + 16 * i) * outPad + oc * 4) = o4;
        } else {
#pragma unroll
            for (int j = 0; j < OC2; j++)
                out2_s[(r0 + 16 * i) * outPad + oc * OC2 + j] = acc2[i][j];
        }
    }
}

__global__ void __launch_bounds__(256, 2)
in2ma_kernel(const float* __restrict__ x,      // (4,64,256,256)
             const float* __restrict__ panf,   // (4,32,256,256)
             const float* __restrict__ Wpq,    // (32,32)
             const float* __restrict__ Wpk,    // (32,32)
             const float* __restrict__ Wv1,    // (64,64)
             const float* __restrict__ Wv2,    // (64,64)
             const float* __restrict__ Wk2,    // (32,64)
             const float* __restrict__ Wq1c,   // (32,64)
             const float* __restrict__ Wk1c,   // (32,64)
             const float* __restrict__ Wio,    // (64,64) inner_out
             const float* __restrict__ Wto,    // (64,64) inter_out
             const float* __restrict__ posI,   // (1,8,64,64)
             const float* __restrict__ posC,   // (1,8,32,32)
             float* __restrict__ out)          // (4,64,256,256)
{
    extern __shared__ float sm[];
    float* A  = sm + OFF_A;
    float* Bv = sm + OFF_B;
    float* C  = sm + OFF_C;
    float* D  = sm + OFF_D;
    float* E  = sm + OFF_E;
    float* WA = sm + OFF_WA;
    float* WB = sm + OFF_WB;

    const int tid = threadIdx.x;
    const int widx = blockIdx.x;
    const int b  = widx >> 10;
    const int hi = (widx >> 5) & 31;
    const int wi = widx & 31;
    const int rowbase = hi * 8;
    const int colbase = wi * 8;

    // ---- load window (float4 along w: 8 consecutive cols = 2 float4 per (ch,row))
    {
        const float* xb = x + b * (64 * 256 * 256) + rowbase * 256 + colbase;
        for (int e = tid; e < 1024; e += 256) {
            int ch = e >> 4;            // 0..63
            int r  = (e >> 1) & 7;      // 0..7
            int c4 = (e & 1) * 4;       // 0 or 4
            float4 v = *reinterpret_cast<const float4*>(xb + ch * 65536 + r * 256 + c4);
            int t = r * 8 + c4;
            A[(t + 0) * P64 + ch] = v.x;
            A[(t + 1) * P64 + ch] = v.y;
            A[(t + 2) * P64 + ch] = v.z;
            A[(t + 3) * P64 + ch] = v.w;
        }
        const float* pb = panf + b * (32 * 256 * 256) + rowbase * 256 + colbase;
        for (int e = tid; e < 512; e += 256) {
            int ch = e >> 4;
            int r  = (e >> 1) & 7;
            int c4 = (e & 1) * 4;
            float4 v = *reinterpret_cast<const float4*>(pb + ch * 65536 + r * 256 + c4);
            int t = r * 8 + c4;
            E[(t + 0) * P32 + ch] = v.x;
            E[(t + 1) * P32 + ch] = v.y;
            E[(t + 2) * P32 + ch] = v.z;
            E[(t + 3) * P32 + ch] = v.w;
        }
        cpw(WA,        Wpq, 1024, tid);
        cpw(WA + 1024, Wpk, 1024, tid);
    }
    __syncthreads();

    // ---- GEMM1: pan_q | pan_k  (C cols 0..31 = q, 32..63 = k), K=32
    gemm_sm<32, 64>(E, P32, WA, C, P64, tid);
    __syncthreads();

    cpw(WA, Wv1, 4096, tid);
    cpw(WB,        Wq1c, 2048, tid);
    cpw(WB + 2048, Wk1c, 2048, tid);
    __syncthreads();

    // ---- GEMM2 (fused): x_v1 -> Bv ; q1c|k1c -> D  (A rows loaded once)
    gemm_sm_dual<64, 64, 64>(A, P64, WA, WB, Bv, D, P64, tid);
    __syncthreads();

    // stage W_inner_out for GEMM3 while attention runs (WA not read until next sync)
    cpw(WA, Wio, 4096, tid);

    const int h = tid >> 5;      // warp = head
    const int lane = tid & 31;

    // ---- inner (pan) attention: warp h, rows i = lane, lane+32.
    {
        const float* pos = posI + h * 4096;
#pragma unroll 1
        for (int p = 0; p < 2; p++) {
            const int i = p * 32 + lane;
            float4 q = *reinterpret_cast<const float4*>(C + i * P64 + h * 4);
            q.x *= SCALE; q.y *= SCALE; q.z *= SCALE; q.w *= SCALE;
            float l[64];
            const float4* pr = reinterpret_cast<const float4*>(pos + i * 64);
#pragma unroll
            for (int j4 = 0; j4 < 16; j4++) {
                float4 pv = pr[j4];
                float pvv[4] = {pv.x, pv.y, pv.z, pv.w};
#pragma unroll
                for (int jj = 0; jj < 4; jj++) {
                    int j = j4 * 4 + jj;
                    float4 k = *reinterpret_cast<const float4*>(C + j * P64 + 32 + h * 4);
                    l[j] = q.x * k.x + q.y * k.y + q.z * k.z + q.w * k.w + pvv[jj];
                }
            }
            float m = l[0];
#pragma unroll
            for (int j = 1; j < 64; j++) m = fmaxf(m, l[j]);
            float ssum = 0.0f;
#pragma unroll
            for (int j = 0; j < 64; j++) { l[j] = __expf(l[j] - m); ssum += l[j]; }
            float inv = 1.0f / ssum;
            float a0 = 0.f, a1 = 0.f, a2 = 0.f, a3 = 0.f;
#pragma unroll
            for (int j = 0; j < 64; j++) {
                float4 v = *reinterpret_cast<const float4*>(Bv + j * P64 + h * 4);
                a0 += l[j] * v.x;
                a1 += l[j] * v.y;
                a2 += l[j] * v.z;
                a3 += l[j] * v.w;
            }
            *reinterpret_cast<float4*>(A + i * P64 + h * 4) =
                make_float4(a0 * inv, a1 * inv, a2 * inv, a3 * inv);
        }
    }

    // ---- color attention: warp h, feature index = lane.
    {
        float qd[8];
#pragma unroll
        for (int d = 0; d < 8; d++)
            qd[d] = D[(h * 8 + d) * P64 + lane] * SCALE;     // q1c[token h*8+d][feat lane]
        float l2[32];
        {
            const float4* pr = reinterpret_cast<const float4*>(posC + h * 1024 + lane * 32);
#pragma unroll
            for (int j4 = 0; j4 < 8; j4++) {
                float4 pv = pr[j4];
                l2[j4 * 4 + 0] = pv.x; l2[j4 * 4 + 1] = pv.y;
                l2[j4 * 4 + 2] = pv.z; l2[j4 * 4 + 3] = pv.w;
            }
        }
#pragma unroll
        for (int d = 0; d < 8; d++) {
            const float4* kr = reinterpret_cast<const float4*>(D + (h * 8 + d) * P64 + 32);
            float qv = qd[d];
#pragma unroll
            for (int j4 = 0; j4 < 8; j4++) {
                float4 kv = kr[j4];
                l2[j4 * 4 + 0] += qv * kv.x;
                l2[j4 * 4 + 1] += qv * kv.y;
                l2[j4 * 4 + 2] += qv * kv.z;
                l2[j4 * 4 + 3] += qv * kv.w;
            }
        }
        float m = l2[0];
#pragma unroll
        for (int j = 1; j < 32; j++) m = fmaxf(m, l2[j]);
        float ssum = 0.0f;
#pragma unroll
        for (int j = 0; j < 32; j++) { l2[j] = __expf(l2[j] - m); ssum += l2[j]; }
        float inv = 1.0f / ssum;
        float accd[8];
#pragma unroll
        for (int d = 0; d < 8; d++) {
            const float4* vr = reinterpret_cast<const float4*>(Bv + (h * 8 + d) * P64 + 32);
            float s = 0.0f;
#pragma unroll
            for (int j4 = 0; j4 < 8; j4++) {
                float4 vv = vr[j4];
                s += l2[j4 * 4 + 0] * vv.x;
                s += l2[j4 * 4 + 1] * vv.y;
                s += l2[j4 * 4 + 2] * vv.z;
                s += l2[j4 * 4 + 3] * vv.w;
            }
            accd[d] = s * inv;
        }
#pragma unroll
        for (int d = 0; d < 8; d++)
            A[(h * 8 + d) * P64 + 32 + lane] = accd[d];          // out_color[t][feat]
    }
    __syncthreads();

    // ---- GEMM3: out1 = cat @ W_inner_out^T  -> Bv
    gemm_sm<64, 64>(A, P64, WA, Bv, P64, tid);
    __syncthreads();

    cpw(WA, Wv2, 4096, tid);
    cpw(WB, Wk2, 2048, tid);
    __syncthreads();

    // ---- GEMM4 (fused): xv2 -> A ; xk2 -> D cols 0..31  (Bv rows loaded once)
    gemm_sm_dual<64, 64, 32>(Bv, P64, WA, WB, A, D, P64, tid);
    __syncthreads();

    // stage W_inter_out; compute cosine gate -> E[h*64+t]
    cpw(WA, Wto, 4096, tid);
    for (int idx = tid; idx < 512; idx += 256) {
        int hh = idx >> 6, t = idx & 63;
        float4 q = *reinterpret_cast<const float4*>(C + t * P64 + hh * 4);   // pan_q
        float4 k = *reinterpret_cast<const float4*>(D + t * P64 + hh * 4);   // xk2
        float dot = q.x * k.x + q.y * k.y + q.z * k.z + q.w * k.w;
        float qq  = q.x * q.x + q.y * q.y + q.z * q.z + q.w * q.w;
        float kk  = k.x * k.x + k.y * k.y + k.z * k.z + k.w * k.w;
        E[idx] = dot / (sqrtf(qq) * sqrtf(kk));
    }
    __syncthreads();

    // ---- out2[t][f] = cos[f/8][t] * xv2[t][f]  -> Bv (float4 along f)
    for (int e = tid; e < 1024; e += 256) {
        int t  = e >> 4;
        int f0 = (e & 15) * 4;
        float g = E[(f0 >> 3) * 64 + t];
        float4 v = *reinterpret_cast<const float4*>(A + t * P64 + f0);
        *reinterpret_cast<float4*>(Bv + t * P64 + f0) =
            make_float4(g * v.x, g * v.y, g * v.z, g * v.w);
    }
    __syncthreads();

    // ---- GEMM5: out3 = out2 @ W_inter_out^T, stored straight to global
    {
        const int r0 = tid & 15;
        const int oc = tid >> 4;
        float acc[4][4];
#pragma unroll
        for (int i = 0; i < 4; i++)
#pragma unroll
            for (int j = 0; j < 4; j++) acc[i][j] = 0.0f;
#pragma unroll
        for (int k4 = 0; k4 < 16; k4++) {
            float4 a[4];
#pragma unroll
            for (int i = 0; i < 4; i++)
                a[i] = *reinterpret_cast<const float4*>(Bv + (r0 + 16 * i) * P64 + 4 * k4);
#pragma unroll
            for (int j = 0; j < 4; j++) {
                float4 w = *reinterpret_cast<const float4*>(WA + (oc * 4 + j) * 64 + 4 * k4);
#pragma unroll
                for (int i = 0; i < 4; i++) {
                    acc[i][j] += a[i].x * w.x;
                    acc[i][j] += a[i].y * w.y;
                    acc[i][j] += a[i].z * w.z;
                    acc[i][j] += a[i].w * w.w;
                }
            }
        }
        float* ob = out + b * (64 * 256 * 256);
#pragma unroll
        for (int i = 0; i < 4; i++) {
            int t = r0 + 16 * i;
            int gr = rowbase + (t >> 3);
            int gc = colbase + (t & 7);
#pragma unroll
            for (int j = 0; j < 4; j++) {
                int o = oc * 4 + j;
                ob[(o * 256 + gr) * 256 + gc] = acc[i][j];
            }
        }
    }
}

} // anonymous namespace

extern "C" void kernel_launch(void* const* d_in, const int* in_sizes, int n_in,
                              void* d_out, int out_size) {
    (void)in_sizes; (void)n_in; (void)out_size;
    const float* x    = (const float*)d_in[0];
    const float* panf = (const float*)d_in[1];
    const float* Wpq  = (const float*)d_in[2];
    const float* Wpk  = (const float*)d_in[3];
    const float* Wv1  = (const float*)d_in[4];
    const float* Wv2  = (const float*)d_in[5];
    const float* Wk2  = (const float*)d_in[6];
    const float* Wq1c = (const float*)d_in[7];
    const float* Wk1c = (const float*)d_in[8];
    const float* Wio  = (const float*)d_in[9];
    const float* Wto  = (const float*)d_in[10];
    const float* posI = (const float*)d_in[11];
    const float* posC = (const float*)d_in[12];
    float* out = (float*)d_out;

    cudaFuncSetAttribute(in2ma_kernel, cudaFuncAttributeMaxDynamicSharedMemorySize, SMEM_BYTES);
    in2ma_kernel<<<4096, 256, SMEM_BYTES>>>(x, panf, Wpq, Wpk, Wv1, Wv2, Wk2,
                                            Wq1c, Wk1c, Wio, Wto, posI, posC, out);
}

// round 11
// speedup vs baseline: 1.5734x; 1.0703x over previous
#include <cuda_runtime.h>
#include <cstdint>
#include <math.h>

// ---------------------------------------------------------------------------
// In2MA fused window kernel, v4b (compile fix of v4):
//  - R8xOC4 GEMM blocking, 128 threads per GEMM (duals use both halves)
//  - weights staged at stride 68 (conflict-free W loads, 1 wavefront)
//  - packed fma.rn.f32x2 in GEMMs + attention AV/color paths
// One CTA per 8x8 window (4096 CTAs), 256 threads.
// ---------------------------------------------------------------------------

namespace {

typedef unsigned long long u64;   // 64-bit, no header dependency

constexpr int P64  = 68;   // activation row stride (float4-aligned, conflict-free)
constexpr int P32  = 36;   // 32-wide activation stride
constexpr int WP64 = 68;   // padded weight stride, K=64 rows
constexpr int WP32 = 36;   // padded weight stride, K=32 rows

// shared memory layout (floats)
constexpr int OFF_A  = 0;                    // xf -> cat -> xv2        [64][68]
constexpr int OFF_B  = OFF_A + 64 * P64;     // v1 -> out1 -> out2      [64][68]
constexpr int OFF_C  = OFF_B + 64 * P64;     // pan_q | pan_k           [64][68]
constexpr int OFF_D  = OFF_C + 64 * P64;     // q1c | k1c -> xk2        [64][68]
constexpr int OFF_E  = OFF_D + 64 * P64;     // pan input -> cos gate   [64][36]
constexpr int OFF_WA = OFF_E + 64 * P32;     // weight buf A  [64][68]
constexpr int OFF_WB = OFF_WA + 64 * WP64;   // weight buf B  [64][68]
constexpr int SMEM_FLOATS = OFF_WB + 64 * WP64;   // 28416 floats
constexpr int SMEM_BYTES  = SMEM_FLOATS * 4;      // 113664 B (2 CTAs/SM)

constexpr float SCALE = 0.35355339059327373f; // 1/sqrt(8)

// ---- packed f32x2 helpers --------------------------------------------------
__device__ __forceinline__ void fma2(u64& d, u64 a, u64 b) {
    asm("fma.rn.f32x2 %0, %1, %2, %0;" : "+l"(d) : "l"(a), "l"(b));
}
__device__ __forceinline__ float hadd2(u64 p) {
    unsigned lo, hi;
    asm("mov.b64 {%0, %1}, %2;" : "=r"(lo), "=r"(hi) : "l"(p));
    return __uint_as_float(lo) + __uint_as_float(hi);
}
__device__ __forceinline__ void upk2(u64 p, float& lo, float& hi) {
    unsigned a, b;
    asm("mov.b64 {%0, %1}, %2;" : "=r"(a), "=r"(b) : "l"(p));
    lo = __uint_as_float(a); hi = __uint_as_float(b);
}
__device__ __forceinline__ u64 pk2(float lo, float hi) {
    u64 r;
    asm("mov.b64 %0, {%1, %2};" : "=l"(r)
        : "r"(__float_as_uint(lo)), "r"(__float_as_uint(hi)));
    return r;
}
union F4U { float4 v; u64 u[2]; };

// ---- weight staging (row stride src 64 or 32 -> padded dst) ----------------
__device__ __forceinline__ void stage_w64(float* dst, const float* src, int rows, int tid) {
    for (int e = tid; e < rows * 16; e += 256) {
        int r = e >> 4, c4 = (e & 15) * 4;
        *reinterpret_cast<float4*>(dst + r * WP64 + c4) =
            *reinterpret_cast<const float4*>(src + r * 64 + c4);
    }
}
__device__ __forceinline__ void stage_w32(float* dst, const float* src, int rows, int tid) {
    for (int e = tid; e < rows * 8; e += 256) {
        int r = e >> 3, c4 = (e & 7) * 4;
        *reinterpret_cast<float4*>(dst + r * WP32 + c4) =
            *reinterpret_cast<const float4*>(src + r * 32 + c4);
    }
}

// ---- GEMM core: out[t][o] = sum_k in[t][k]*W[o][k], 64 rows, O cols --------
// 128 threads: r0 = t&7 (rows r0+8i, i<8), oc = t>>3 (cols oc+16j, j<O/16).
// Warp spans 8 A-rows (1 wf/load, broadcast) and 4 W-rows (1 wf/load).
template <int K, int O, int WPAD>
__device__ __forceinline__ void gemm128(const float* __restrict__ in_s, int inPad,
                                        const float* __restrict__ w_s,
                                        float* __restrict__ out_s, int outPad, int t) {
    const int r0 = t & 7;
    const int oc = t >> 3;             // 0..15
    constexpr int OC = O / 16;          // 2 or 4
    u64 acc[8][OC];
#pragma unroll
    for (int i = 0; i < 8; i++)
#pragma unroll
        for (int j = 0; j < OC; j++) acc[i][j] = 0ull;

#pragma unroll 4
    for (int k4 = 0; k4 < K / 4; k4++) {
        F4U w[OC];
#pragma unroll
        for (int j = 0; j < OC; j++)
            w[j].v = *reinterpret_cast<const float4*>(w_s + (oc + 16 * j) * WPAD + 4 * k4);
#pragma unroll
        for (int i = 0; i < 8; i++) {
            F4U a;
            a.v = *reinterpret_cast<const float4*>(in_s + (r0 + 8 * i) * inPad + 4 * k4);
#pragma unroll
            for (int j = 0; j < OC; j++) {
                fma2(acc[i][j], a.u[0], w[j].u[0]);
                fma2(acc[i][j], a.u[1], w[j].u[1]);
            }
        }
    }
#pragma unroll
    for (int i = 0; i < 8; i++)
#pragma unroll
        for (int j = 0; j < OC; j++)
            out_s[(r0 + 8 * i) * outPad + oc + 16 * j] = hadd2(acc[i][j]);
}

__global__ void __launch_bounds__(256, 2)
in2ma_kernel(const float* __restrict__ x,      // (4,64,256,256)
             const float* __restrict__ panf,   // (4,32,256,256)
             const float* __restrict__ Wpq,    // (32,32)
             const float* __restrict__ Wpk,    // (32,32)
             const float* __restrict__ Wv1,    // (64,64)
             const float* __restrict__ Wv2,    // (64,64)
             const float* __restrict__ Wk2,    // (32,64)
             const float* __restrict__ Wq1c,   // (32,64)
             const float* __restrict__ Wk1c,   // (32,64)
             const float* __restrict__ Wio,    // (64,64)
             const float* __restrict__ Wto,    // (64,64)
             const float* __restrict__ posI,   // (1,8,64,64)
             const float* __restrict__ posC,   // (1,8,32,32)
             float* __restrict__ out)          // (4,64,256,256)
{
    extern __shared__ float sm[];
    float* A  = sm + OFF_A;
    float* Bv = sm + OFF_B;
    float* C  = sm + OFF_C;
    float* D  = sm + OFF_D;
    float* E  = sm + OFF_E;
    float* WA = sm + OFF_WA;
    float* WB = sm + OFF_WB;

    const int tid = threadIdx.x;
    const int widx = blockIdx.x;
    const int b  = widx >> 10;
    const int hi = (widx >> 5) & 31;
    const int wi = widx & 31;
    const int rowbase = hi * 8;
    const int colbase = wi * 8;

    // ---- load window tiles + GEMM1 weights
    {
        const float* xb = x + b * (64 * 256 * 256) + rowbase * 256 + colbase;
        for (int e = tid; e < 1024; e += 256) {
            int ch = e >> 4;
            int r  = (e >> 1) & 7;
            int c4 = (e & 1) * 4;
            float4 v = *reinterpret_cast<const float4*>(xb + ch * 65536 + r * 256 + c4);
            int t = r * 8 + c4;
            A[(t + 0) * P64 + ch] = v.x;
            A[(t + 1) * P64 + ch] = v.y;
            A[(t + 2) * P64 + ch] = v.z;
            A[(t + 3) * P64 + ch] = v.w;
        }
        const float* pb = panf + b * (32 * 256 * 256) + rowbase * 256 + colbase;
        for (int e = tid; e < 512; e += 256) {
            int ch = e >> 4;
            int r  = (e >> 1) & 7;
            int c4 = (e & 1) * 4;
            float4 v = *reinterpret_cast<const float4*>(pb + ch * 65536 + r * 256 + c4);
            int t = r * 8 + c4;
            E[(t + 0) * P32 + ch] = v.x;
            E[(t + 1) * P32 + ch] = v.y;
            E[(t + 2) * P32 + ch] = v.z;
            E[(t + 3) * P32 + ch] = v.w;
        }
        stage_w32(WA,             Wpq, 32, tid);   // rows 0..31 of combined [64][36]
        stage_w32(WA + 32 * WP32, Wpk, 32, tid);   // rows 32..63
    }
    __syncthreads();

    // ---- GEMM1: pan_q | pan_k  (C cols 0..31 q, 32..63 k), K=32
    if (tid < 128)
        gemm128<32, 64, WP32>(E, P32, WA, C, P64, tid);
    __syncthreads();

    stage_w64(WA, Wv1, 64, tid);
    stage_w64(WB,             Wq1c, 32, tid);
    stage_w64(WB + 32 * WP64, Wk1c, 32, tid);
    __syncthreads();

    // ---- GEMM2 (dual halves): x_v1 -> Bv ; q1c|k1c -> D
    if (tid < 128)
        gemm128<64, 64, WP64>(A, P64, WA, Bv, P64, tid);
    else
        gemm128<64, 64, WP64>(A, P64, WB, D, P64, tid - 128);
    __syncthreads();

    // stage W_inner_out during attention (WA not read until GEMM3)
    stage_w64(WA, Wio, 64, tid);

    const int h = tid >> 5;      // warp = head
    const int lane = tid & 31;

    // ---- inner (pan) attention: warp h, rows i = lane, lane+32.
    {
        const float* pos = posI + h * 4096;
#pragma unroll 1
        for (int p = 0; p < 2; p++) {
            const int i = p * 32 + lane;
            float4 q = *reinterpret_cast<const float4*>(C + i * P64 + h * 4);
            q.x *= SCALE; q.y *= SCALE; q.z *= SCALE; q.w *= SCALE;
            float l[64];
            const float4* pr = reinterpret_cast<const float4*>(pos + i * 64);
#pragma unroll
            for (int j4 = 0; j4 < 16; j4++) {
                float4 pv = pr[j4];
                float pvv[4] = {pv.x, pv.y, pv.z, pv.w};
#pragma unroll
                for (int jj = 0; jj < 4; jj++) {
                    int j = j4 * 4 + jj;
                    float4 k = *reinterpret_cast<const float4*>(C + j * P64 + 32 + h * 4);
                    l[j] = q.x * k.x + q.y * k.y + q.z * k.z + q.w * k.w + pvv[jj];
                }
            }
            float m = l[0];
#pragma unroll
            for (int j = 1; j < 64; j++) m = fmaxf(m, l[j]);
            float ssum = 0.0f;
#pragma unroll
            for (int j = 0; j < 64; j++) { l[j] = __expf(l[j] - m); ssum += l[j]; }
            float inv = 1.0f / ssum;
            // AV with packed f32x2
            u64 acc01 = 0ull, acc23 = 0ull;
#pragma unroll
            for (int j = 0; j < 64; j++) {
                F4U vv;
                vv.v = *reinterpret_cast<const float4*>(Bv + j * P64 + h * 4);
                u64 lj = pk2(l[j], l[j]);
                fma2(acc01, lj, vv.u[0]);
                fma2(acc23, lj, vv.u[1]);
            }
            float a0, a1, a2, a3;
            upk2(acc01, a0, a1);
            upk2(acc23, a2, a3);
            *reinterpret_cast<float4*>(A + i * P64 + h * 4) =
                make_float4(a0 * inv, a1 * inv, a2 * inv, a3 * inv);
        }
    }

    // ---- color attention: warp h, feature index = lane (packed over j-pairs)
    {
        float qd[8];
#pragma unroll
        for (int d = 0; d < 8; d++)
            qd[d] = D[(h * 8 + d) * P64 + lane] * SCALE;
        u64 pl2[16];
        {
            const float4* pr = reinterpret_cast<const float4*>(posC + h * 1024 + lane * 32);
#pragma unroll
            for (int j4 = 0; j4 < 8; j4++) {
                F4U pv; pv.v = pr[j4];
                pl2[2 * j4]     = pv.u[0];
                pl2[2 * j4 + 1] = pv.u[1];
            }
        }
#pragma unroll
        for (int d = 0; d < 8; d++) {
            u64 qp = pk2(qd[d], qd[d]);
            const float4* kr = reinterpret_cast<const float4*>(D + (h * 8 + d) * P64 + 32);
#pragma unroll
            for (int j4 = 0; j4 < 8; j4++) {
                F4U kv; kv.v = kr[j4];
                fma2(pl2[2 * j4],     qp, kv.u[0]);
                fma2(pl2[2 * j4 + 1], qp, kv.u[1]);
            }
        }
        float l2[32];
#pragma unroll
        for (int mz = 0; mz < 16; mz++)
            upk2(pl2[mz], l2[2 * mz], l2[2 * mz + 1]);
        float m = l2[0];
#pragma unroll
        for (int j = 1; j < 32; j++) m = fmaxf(m, l2[j]);
        float ssum = 0.0f;
#pragma unroll
        for (int j = 0; j < 32; j++) { l2[j] = __expf(l2[j] - m); ssum += l2[j]; }
        float inv = 1.0f / ssum;
#pragma unroll
        for (int mz = 0; mz < 16; mz++)
            pl2[mz] = pk2(l2[2 * mz], l2[2 * mz + 1]);
        float accd[8];
#pragma unroll
        for (int d = 0; d < 8; d++) {
            const float4* vr = reinterpret_cast<const float4*>(Bv + (h * 8 + d) * P64 + 32);
            u64 s = 0ull;
#pragma unroll
            for (int j4 = 0; j4 < 8; j4++) {
                F4U vv; vv.v = vr[j4];
                fma2(s, pl2[2 * j4],     vv.u[0]);
                fma2(s, pl2[2 * j4 + 1], vv.u[1]);
            }
            accd[d] = hadd2(s) * inv;
        }
#pragma unroll
        for (int d = 0; d < 8; d++)
            A[(h * 8 + d) * P64 + 32 + lane] = accd[d];
    }
    __syncthreads();

    // ---- GEMM3: out1 = cat @ W_inner_out^T -> Bv
    if (tid < 128)
        gemm128<64, 64, WP64>(A, P64, WA, Bv, P64, tid);
    __syncthreads();

    stage_w64(WA, Wv2, 64, tid);
    stage_w64(WB, Wk2, 32, tid);
    __syncthreads();

    // ---- GEMM4 (dual halves): xv2 -> A ; xk2 -> D cols 0..31
    if (tid < 128)
        gemm128<64, 64, WP64>(Bv, P64, WA, A, P64, tid);
    else
        gemm128<64, 32, WP64>(Bv, P64, WB, D, P64, tid - 128);
    __syncthreads();

    // stage W_inter_out; cosine gate -> E[h*64+t]
    stage_w64(WA, Wto, 64, tid);
    for (int idx = tid; idx < 512; idx += 256) {
        int hh = idx >> 6, t = idx & 63;
        float4 q = *reinterpret_cast<const float4*>(C + t * P64 + hh * 4);
        float4 k = *reinterpret_cast<const float4*>(D + t * P64 + hh * 4);
        float dot = q.x * k.x + q.y * k.y + q.z * k.z + q.w * k.w;
        float qq  = q.x * q.x + q.y * q.y + q.z * q.z + q.w * q.w;
        float kk  = k.x * k.x + k.y * k.y + k.z * k.z + k.w * k.w;
        E[idx] = dot / (sqrtf(qq) * sqrtf(kk));
    }
    __syncthreads();

    // ---- out2[t][f] = cos[f/8][t] * xv2[t][f] -> Bv
    for (int e = tid; e < 1024; e += 256) {
        int t  = e >> 4;
        int f0 = (e & 15) * 4;
        float g = E[(f0 >> 3) * 64 + t];
        float4 v = *reinterpret_cast<const float4*>(A + t * P64 + f0);
        *reinterpret_cast<float4*>(Bv + t * P64 + f0) =
            make_float4(g * v.x, g * v.y, g * v.z, g * v.w);
    }
    __syncthreads();

    // ---- GEMM5: out3 = out2 @ W_inter_out^T -> global (R8xOC4, 128 threads)
    if (tid < 128) {
        const int r0 = tid & 7;
        const int oc = tid >> 3;
        u64 acc[8][4];
#pragma unroll
        for (int i = 0; i < 8; i++)
#pragma unroll
            for (int j = 0; j < 4; j++) acc[i][j] = 0ull;
#pragma unroll 4
        for (int k4 = 0; k4 < 16; k4++) {
            F4U w[4];
#pragma unroll
            for (int j = 0; j < 4; j++)
                w[j].v = *reinterpret_cast<const float4*>(WA + (oc + 16 * j) * WP64 + 4 * k4);
#pragma unroll
            for (int i = 0; i < 8; i++) {
                F4U a;
                a.v = *reinterpret_cast<const float4*>(Bv + (r0 + 8 * i) * P64 + 4 * k4);
#pragma unroll
                for (int j = 0; j < 4; j++) {
                    fma2(acc[i][j], a.u[0], w[j].u[0]);
                    fma2(acc[i][j], a.u[1], w[j].u[1]);
                }
            }
        }
        float* ob = out + b * (64 * 256 * 256);
#pragma unroll
        for (int i = 0; i < 8; i++) {
            int t = r0 + 8 * i;
            int gr = rowbase + (t >> 3);
            int gc = colbase + (t & 7);
#pragma unroll
            for (int j = 0; j < 4; j++) {
                int o = oc + 16 * j;
                ob[(o * 256 + gr) * 256 + gc] = hadd2(acc[i][j]);
            }
        }
    }
}

} // anonymous namespace

extern "C" void kernel_launch(void* const* d_in, const int* in_sizes, int n_in,
                              void* d_out, int out_size) {
    (void)in_sizes; (void)n_in; (void)out_size;
    const float* x    = (const float*)d_in[0];
    const float* panf = (const float*)d_in[1];
    const float* Wpq  = (const float*)d_in[2];
    const float* Wpk  = (const float*)d_in[3];
    const float* Wv1  = (const float*)d_in[4];
    const float* Wv2  = (const float*)d_in[5];
    const float* Wk2  = (const float*)d_in[6];
    const float* Wq1c = (const float*)d_in[7];
    const float* Wk1c = (const float*)d_in[8];
    const float* Wio  = (const float*)d_in[9];
    const float* Wto  = (const float*)d_in[10];
    const float* posI = (const float*)d_in[11];
    const float* posC = (const float*)d_in[12];
    float* out = (float*)d_out;

    cudaFuncSetAttribute(in2ma_kernel, cudaFuncAttributeMaxDynamicSharedMemorySize, SMEM_BYTES);
    in2ma_kernel<<<4096, 256, SMEM_BYTES>>>(x, panf, Wpq, Wpk, Wv1, Wv2, Wk2,
                                            Wq1c, Wk1c, Wio, Wto, posI, posC, out);
}